// round 15
// baseline (speedup 1.0000x reference)
#include <cuda_runtime.h>
#include <cuda_bf16.h>
#include <cstddef>

// LengthRegulator, single fused kernel (R13 theory, third submission — the
// prior two attempts hit infra GPUAcquisitionTimeout before running; all
// __syncthreads are executed unconditionally by all 1024 threads):
//   Block = 64 output frames of one batch, 1024 threads (halves the number
//   of redundant scan prologues vs R12's 32-frame/512-thread blocks; the
//   per-thread copy shape is IDENTICAL: 8 independent vec4s, consecutive
//   frames, __stcs streaming stores).
// B=16, S=512, H=512 fixed; T derived from out_size.

#define LR_B   16
#define LR_S   512
#define LR_V   128        // float4 per row (H=512)
#define LR_FPB 64         // frames per block
#define LR_THR 1024

__global__ __launch_bounds__(LR_THR)
void lr_fused_kernel(const float4* __restrict__ x4,
                     const int*    __restrict__ dur,
                     float4*       __restrict__ out4,
                     int T)
{
    __shared__ int cum[LR_S];
    __shared__ int sh_w[16];
    __shared__ int sidx[LR_FPB];

    const int b    = blockIdx.y;
    const int f0   = blockIdx.x * LR_FPB;
    const int tid  = threadIdx.x;
    const int wid  = tid >> 5;        // 0..31
    const int lane = tid & 31;

    // ---- warp-shuffle inclusive scan of durations[b, :] ----
    // Warps 0..15 (tid < 512) do the scan work; barriers are unconditional.
    int v = 0;
    if (tid < LR_S) {
        v = dur[b * LR_S + tid];
#pragma unroll
        for (int off = 1; off < 32; off <<= 1) {
            int n = __shfl_up_sync(0xFFFFFFFFu, v, off);
            if (lane >= off) v += n;
        }
        if (lane == 31) sh_w[wid] = v;
    }
    __syncthreads();
    if (wid == 0 && lane < 16) {
        int w  = sh_w[lane];
        int vv = w;
#pragma unroll
        for (int off = 1; off < 16; off <<= 1) {
            int n = __shfl_up_sync(0xFFFFu, vv, off);
            if (lane >= off) vv += n;
        }
        sh_w[lane] = vv - w;          // exclusive warp offset
    }
    __syncthreads();
    if (tid < LR_S)
        cum[tid] = v + sh_w[wid];     // inclusive cumsum
    __syncthreads();

    // ---- searchsorted(right) for this block's 64 frames ----
    if (tid < LR_FPB) {
        int t = f0 + tid;
        int lo = 0, hi = LR_S;
        while (lo < hi) {
            int mid = (lo + hi) >> 1;
            if (cum[mid] <= t) lo = mid + 1; else hi = mid;
        }
        sidx[tid] = (lo < LR_S) ? (b * LR_S + lo) : -1;
    }
    __syncthreads();

    // ---- copy: thread = column e of 8 consecutive frames ----
    // g in {0..7}: frames [g*8, g*8+8). Consecutive frames share source rows
    // (avg duration ~7.5) -> most of the 8 loads are L1 same-line hits.
    const int g = tid >> 7;           // 0..7
    const int e = tid & 127;          // vec4 column within row

    float4 val[8];
#pragma unroll
    for (int j = 0; j < 8; j++) {
        int row = sidx[g * 8 + j];
        val[j] = make_float4(0.f, 0.f, 0.f, 0.f);
        if (row >= 0)
            val[j] = __ldg(&x4[(size_t)row * LR_V + e]);
    }

    float4* base = out4 + ((size_t)b * T + f0) * LR_V;
#pragma unroll
    for (int j = 0; j < 8; j++)
        __stcs(&base[(g * 8 + j) * LR_V + e], val[j]);   // streaming store
}

// ---------------- generic fallback (any shape; unused here) ----------------
__global__ void lr_generic_kernel(const float* __restrict__ x,
                                  const int* __restrict__ dur,
                                  float* __restrict__ out,
                                  int B, int S, int H, int T)
{
    size_t i = (size_t)blockIdx.x * blockDim.x + threadIdx.x;
    size_t total = (size_t)B * T * H;
    if (i >= total) return;
    int e = (int)(i % H);
    int t = (int)((i / H) % T);
    int b = (int)(i / ((size_t)T * H));
    int c = 0, idx = S;
    for (int j = 0; j < S; j++) { c += dur[b * S + j]; if (c > t) { idx = j; break; } }
    out[i] = (idx < S) ? x[((size_t)b * S + idx) * H + e] : 0.f;
}

extern "C" void kernel_launch(void* const* d_in, const int* in_sizes, int n_in,
                              void* d_out, int out_size)
{
    const float* x   = (const float*)d_in[0];
    const int*   dur = (const int*)d_in[1];
    float*       out = (float*)d_out;

    const int BS = in_sizes[1];              // B * S = 8192
    const int H  = in_sizes[0] / BS;         // 512
    const int T  = out_size / (LR_B * H);    // 4096
    const int S  = BS / LR_B;

    if (H == 512 && S == LR_S && (T % LR_FPB) == 0) {
        dim3 grid(T / LR_FPB, LR_B);
        lr_fused_kernel<<<grid, LR_THR>>>((const float4*)x, dur,
                                          (float4*)out, T);
    } else {
        size_t total = (size_t)out_size;
        int blocks = (int)((total + 255) / 256);
        lr_generic_kernel<<<blocks, 256>>>(x, dur, out, LR_B, S, H, T);
    }
}